// round 3
// baseline (speedup 1.0000x reference)
#include <cuda_runtime.h>
#include <cuda_bf16.h>

#define GAMMAK (1.0f/256.0f)
#define NROWS 8191            // valid query/key rows
#define D 128

// ---------------- scratch (device globals: no allocation allowed) ----------
__device__ float g_yt[8192 * 128];   // yt padded to 8192 rows
__device__ float g_kn[8192];         // ||yt_j||^2, padded row -> 1e30 (weight 0)
__device__ float g_qn[8192];         // ||X_i||^2

// ---------------- kernel 1: yt = y @ R^T + t  (64 rows / CTA) --------------
// smem: yT [128][68] transposed  (34816 B)  +  RT [128][132] transposed (67584 B)
__global__ __launch_bounds__(256) void yt_kernel(const float* __restrict__ y,
                                                 const float* __restrict__ R,
                                                 const float* __restrict__ t)
{
    extern __shared__ char smem[];
    float* yT = (float*)smem;                 // [k][row] stride 68
    float* RT = (float*)(smem + 34816);       // [k][c]   stride 132
    const int tid = threadIdx.x;
    const int r0  = blockIdx.x * 64;

    // load y tile transposed (coalesced gmem, 4-way-conflict STS at worst)
    #pragma unroll
    for (int s = 0; s < 32; s++) {
        int e = tid + s * 256;                // 0..8191
        int row = e >> 7, k = e & 127;
        int gr = r0 + row;
        float v = (gr < NROWS) ? y[gr * 128 + k] : 0.0f;
        yT[k * 68 + row] = v;
    }
    // load R transposed: RT[k][c] = R[c][k]
    #pragma unroll
    for (int s = 0; s < 64; s++) {
        int e = tid + s * 256;                // 0..16383
        int c = e >> 7, k = e & 127;
        RT[k * 132 + c] = R[e];
    }
    __syncthreads();

    const int tr = tid >> 4, tc = tid & 15;   // 16x16 threads, 4 rows x 8 cols each
    float acc[4][8];
    #pragma unroll
    for (int i = 0; i < 4; i++)
        #pragma unroll
        for (int j = 0; j < 8; j++) acc[i][j] = 0.0f;

    const float4* yT4 = (const float4*)yT;    // row stride 17 float4
    const float4* RT4 = (const float4*)RT;    // row stride 33 float4

    #pragma unroll 8
    for (int k = 0; k < 128; k++) {
        float4 a  = yT4[k * 17 + tr];
        float4 b0 = RT4[k * 33 + tc * 2];
        float4 b1 = RT4[k * 33 + tc * 2 + 1];
        float av[4] = {a.x, a.y, a.z, a.w};
        float bv[8] = {b0.x, b0.y, b0.z, b0.w, b1.x, b1.y, b1.z, b1.w};
        #pragma unroll
        for (int i = 0; i < 4; i++)
            #pragma unroll
            for (int j = 0; j < 8; j++) acc[i][j] += av[i] * bv[j];
    }

    float tv[8];
    #pragma unroll
    for (int j = 0; j < 8; j++) tv[j] = t[tc * 8 + j];

    float4* yt4 = (float4*)g_yt;
    #pragma unroll
    for (int i = 0; i < 4; i++) {
        int row = r0 + tr * 4 + i;
        float4 o0, o1;
        o0.x = acc[i][0] + tv[0];  o0.y = acc[i][1] + tv[1];
        o0.z = acc[i][2] + tv[2];  o0.w = acc[i][3] + tv[3];
        o1.x = acc[i][4] + tv[4];  o1.y = acc[i][5] + tv[5];
        o1.z = acc[i][6] + tv[6];  o1.w = acc[i][7] + tv[7];
        yt4[row * 32 + tc * 2]     = o0;
        yt4[row * 32 + tc * 2 + 1] = o1;
    }
}

// ---------------- kernel 2: row sum-of-squares for X (qn) and yt (kn) ------
__global__ __launch_bounds__(128) void norm_kernel(const float* __restrict__ X)
{
    const int row   = blockIdx.x;
    const int which = blockIdx.y;             // 0 -> qn(X), 1 -> kn(yt)
    const float* src = which ? g_yt : X;
    float v = src[row * 128 + threadIdx.x];
    float s = v * v;
    #pragma unroll
    for (int o = 16; o; o >>= 1) s += __shfl_down_sync(0xFFFFFFFFu, s, o);
    __shared__ float red[4];
    if ((threadIdx.x & 31) == 0) red[threadIdx.x >> 5] = s;
    __syncthreads();
    if (threadIdx.x == 0) {
        float tot = red[0] + red[1] + red[2] + red[3];
        if (which) g_kn[row] = (row < NROWS) ? tot : 1e30f;  // pad key -> weight 0
        else       g_qn[row] = tot;
    }
}

// ---------------- kernel 3: fused RBF attention ----------------------------
// BM=64 queries/CTA, BN=64 keys/tile, d=128. 256 threads (16x16).
// smem layout (bytes):
//   Qt  [128][68]  @ 0       (34816)
//   Kt  [128][68]  @ 34816   (34816)
//   Vs  [64][128]  @ 69632   (32768)
//   Pt  [64][68]   @ 102400  (17408)   -- P transposed: [key][query]
//   qn_s[64]       @ 119808
//   kn_s[64]       @ 120064
// total 120320 B
__global__ __launch_bounds__(256) void attn_kernel(const float* __restrict__ X,
                                                   float* __restrict__ out)
{
    extern __shared__ char smem[];
    float* Qt   = (float*)smem;
    float* Kt   = (float*)(smem + 34816);
    float* Vs   = (float*)(smem + 69632);
    float* Pt   = (float*)(smem + 102400);
    float* qn_s = (float*)(smem + 119808);
    float* kn_s = (float*)(smem + 120064);

    const int tid = threadIdx.x;
    const int tr  = tid >> 4, tc = tid & 15;
    const int r0  = blockIdx.x * 64;

    // Q tile (X rows r0..r0+63; row 8191 exists in X, output guarded later)
    #pragma unroll
    for (int s = 0; s < 32; s++) {
        int e = tid + s * 256;
        int row = e >> 7, k = e & 127;
        Qt[k * 68 + row] = X[(r0 + row) * 128 + k];
    }
    if (tid < 64) qn_s[tid] = g_qn[r0 + tid];
    __syncthreads();

    float acc[4][8];
    float den[4] = {0.f, 0.f, 0.f, 0.f};
    #pragma unroll
    for (int i = 0; i < 4; i++)
        #pragma unroll
        for (int j = 0; j < 8; j++) acc[i][j] = 0.0f;

    const float4* Qt4 = (const float4*)Qt;   // stride 17
    const float4* Kt4 = (const float4*)Kt;   // stride 17
    const float4* Vs4 = (const float4*)Vs;   // stride 32
    float4*       VsW = (float4*)Vs;
    const float4* Pt4 = (const float4*)Pt;   // stride 17
    float4*       PtW = (float4*)Pt;
    const float4* X4  = (const float4*)X;

    float qnv[4];
    #pragma unroll
    for (int i = 0; i < 4; i++) qnv[i] = qn_s[tr * 4 + i];

    for (int tile = 0; tile < 128; tile++) {
        const int j0 = tile * 64;

        // ---- stage K (transposed), V, kn ----
        #pragma unroll
        for (int s = 0; s < 32; s++) {
            int e = tid + s * 256;
            int row = e >> 7, k = e & 127;
            Kt[k * 68 + row] = g_yt[(j0 + row) * 128 + k];
        }
        #pragma unroll
        for (int s = 0; s < 8; s++) {
            int idx = tid + s * 256;          // float4 index 0..2047
            int row = idx >> 5, c4 = idx & 31;
            int jg = j0 + row;
            float4 v = (jg < NROWS) ? X4[(jg + 1) * 32 + c4]
                                    : make_float4(0.f, 0.f, 0.f, 0.f);
            VsW[row * 32 + c4] = v;
        }
        if (tid < 64) kn_s[tid] = g_kn[j0 + tid];
        __syncthreads();

        // ---- S = Q @ K^T (4x4 per thread) ----
        float sa[4][4];
        #pragma unroll
        for (int i = 0; i < 4; i++)
            #pragma unroll
            for (int j = 0; j < 4; j++) sa[i][j] = 0.0f;

        #pragma unroll 8
        for (int k = 0; k < 128; k++) {
            float4 a = Qt4[k * 17 + tr];
            float4 b = Kt4[k * 17 + tc];
            float av[4] = {a.x, a.y, a.z, a.w};
            float bv[4] = {b.x, b.y, b.z, b.w};
            #pragma unroll
            for (int i = 0; i < 4; i++)
                #pragma unroll
                for (int j = 0; j < 4; j++) sa[i][j] += av[i] * bv[j];
        }

        // ---- P = exp(-gamma * clip(qn + kn - 2S, 0)) ; store transposed ----
        #pragma unroll
        for (int j = 0; j < 4; j++) {
            float knc = kn_s[tc * 4 + j];
            float4 p;
            p.x = __expf(-GAMMAK * fmaxf(fmaf(-2.0f, sa[0][j], qnv[0] + knc), 0.0f));
            p.y = __expf(-GAMMAK * fmaxf(fmaf(-2.0f, sa[1][j], qnv[1] + knc), 0.0f));
            p.z = __expf(-GAMMAK * fmaxf(fmaf(-2.0f, sa[2][j], qnv[2] + knc), 0.0f));
            p.w = __expf(-GAMMAK * fmaxf(fmaf(-2.0f, sa[3][j], qnv[3] + knc), 0.0f));
            PtW[(tc * 4 + j) * 17 + tr] = p;  // Pt[key][query], STS.128
        }
        __syncthreads();

        // ---- acc += P @ V ; den += rowsum(P) ----
        #pragma unroll 4
        for (int j = 0; j < 64; j++) {
            float4 p  = Pt4[j * 17 + tr];
            float4 v0 = Vs4[j * 32 + tc * 2];
            float4 v1 = Vs4[j * 32 + tc * 2 + 1];
            float pa[4] = {p.x, p.y, p.z, p.w};
            float vv[8] = {v0.x, v0.y, v0.z, v0.w, v1.x, v1.y, v1.z, v1.w};
            #pragma unroll
            for (int i = 0; i < 4; i++) {
                den[i] += pa[i];
                #pragma unroll
                for (int c = 0; c < 8; c++) acc[i][c] += pa[i] * vv[c];
            }
        }
        __syncthreads();   // before next tile overwrites Kt/Vs/kn_s
    }

    // ---- normalize + write ----
    float4* out4 = (float4*)out;
    #pragma unroll
    for (int i = 0; i < 4; i++) {
        int row = r0 + tr * 4 + i;
        if (row < NROWS) {
            float inv = 1.0f / den[i];
            float4 o0, o1;
            o0.x = acc[i][0] * inv;  o0.y = acc[i][1] * inv;
            o0.z = acc[i][2] * inv;  o0.w = acc[i][3] * inv;
            o1.x = acc[i][4] * inv;  o1.y = acc[i][5] * inv;
            o1.z = acc[i][6] * inv;  o1.w = acc[i][7] * inv;
            out4[row * 32 + tc * 2]     = o0;
            out4[row * 32 + tc * 2 + 1] = o1;
        }
    }
}

// ---------------- launch ----------------------------------------------------
extern "C" void kernel_launch(void* const* d_in, const int* in_sizes, int n_in,
                              void* d_out, int out_size)
{
    const float* X = (const float*)d_in[0];   // (8192,128)
    const float* y = (const float*)d_in[1];   // (8191,128)
    // d_in[2] = y_next : unused by reference output
    const float* R = (const float*)d_in[3];   // (128,128)
    const float* t = (const float*)d_in[4];   // (128,1)
    float* out = (float*)d_out;               // (8191,128)

    cudaFuncSetAttribute(yt_kernel,  cudaFuncAttributeMaxDynamicSharedMemorySize, 102400);
    cudaFuncSetAttribute(attn_kernel, cudaFuncAttributeMaxDynamicSharedMemorySize, 120320);

    yt_kernel<<<128, 256, 102400>>>(y, R, t);
    norm_kernel<<<dim3(8192, 2), 128>>>(X);
    attn_kernel<<<128, 256, 120320>>>(X, out);
}

// round 4
// speedup vs baseline: 1.0010x; 1.0010x over previous
#include <cuda_runtime.h>
#include <cuda_bf16.h>

#define GAMMAK (1.0f/256.0f)
#define NROWS 8191            // valid query/key rows
#define D 128

// ---------------- scratch (device globals: no allocation allowed) ----------
__device__ float g_yt[8192 * 128];   // yt padded to 8192 rows
__device__ float g_kn[8192];         // ||yt_j||^2, padded row -> 1e30 (weight 0)
__device__ float g_qn[8192];         // ||X_i||^2

// ---------------- kernel 1: yt = y @ R^T + t  (64 rows / CTA) --------------
// smem: yT [128][68] transposed  (34816 B)  +  RT [128][132] transposed (67584 B)
__global__ __launch_bounds__(256) void yt_kernel(const float* __restrict__ y,
                                                 const float* __restrict__ R,
                                                 const float* __restrict__ t)
{
    extern __shared__ char smem[];
    float* yT = (float*)smem;                 // [k][row] stride 68
    float* RT = (float*)(smem + 34816);       // [k][c]   stride 132
    const int tid = threadIdx.x;
    const int r0  = blockIdx.x * 64;

    // load y tile transposed (coalesced gmem, 4-way-conflict STS at worst)
    #pragma unroll
    for (int s = 0; s < 32; s++) {
        int e = tid + s * 256;                // 0..8191
        int row = e >> 7, k = e & 127;
        int gr = r0 + row;
        float v = (gr < NROWS) ? y[gr * 128 + k] : 0.0f;
        yT[k * 68 + row] = v;
    }
    // load R transposed: RT[k][c] = R[c][k]
    #pragma unroll
    for (int s = 0; s < 64; s++) {
        int e = tid + s * 256;                // 0..16383
        int c = e >> 7, k = e & 127;
        RT[k * 132 + c] = R[e];
    }
    __syncthreads();

    const int tr = tid >> 4, tc = tid & 15;   // 16x16 threads, 4 rows x 8 cols each
    float acc[4][8];
    #pragma unroll
    for (int i = 0; i < 4; i++)
        #pragma unroll
        for (int j = 0; j < 8; j++) acc[i][j] = 0.0f;

    const float4* yT4 = (const float4*)yT;    // row stride 17 float4
    const float4* RT4 = (const float4*)RT;    // row stride 33 float4

    #pragma unroll 8
    for (int k = 0; k < 128; k++) {
        float4 a  = yT4[k * 17 + tr];
        float4 b0 = RT4[k * 33 + tc * 2];
        float4 b1 = RT4[k * 33 + tc * 2 + 1];
        float av[4] = {a.x, a.y, a.z, a.w};
        float bv[8] = {b0.x, b0.y, b0.z, b0.w, b1.x, b1.y, b1.z, b1.w};
        #pragma unroll
        for (int i = 0; i < 4; i++)
            #pragma unroll
            for (int j = 0; j < 8; j++) acc[i][j] += av[i] * bv[j];
    }

    float tv[8];
    #pragma unroll
    for (int j = 0; j < 8; j++) tv[j] = t[tc * 8 + j];

    float4* yt4 = (float4*)g_yt;
    #pragma unroll
    for (int i = 0; i < 4; i++) {
        int row = r0 + tr * 4 + i;
        float4 o0, o1;
        o0.x = acc[i][0] + tv[0];  o0.y = acc[i][1] + tv[1];
        o0.z = acc[i][2] + tv[2];  o0.w = acc[i][3] + tv[3];
        o1.x = acc[i][4] + tv[4];  o1.y = acc[i][5] + tv[5];
        o1.z = acc[i][6] + tv[6];  o1.w = acc[i][7] + tv[7];
        yt4[row * 32 + tc * 2]     = o0;
        yt4[row * 32 + tc * 2 + 1] = o1;
    }
}

// ---------------- kernel 2: row sum-of-squares for X (qn) and yt (kn) ------
__global__ __launch_bounds__(128) void norm_kernel(const float* __restrict__ X)
{
    const int row   = blockIdx.x;
    const int which = blockIdx.y;             // 0 -> qn(X), 1 -> kn(yt)
    const float* src = which ? g_yt : X;
    float v = src[row * 128 + threadIdx.x];
    float s = v * v;
    #pragma unroll
    for (int o = 16; o; o >>= 1) s += __shfl_down_sync(0xFFFFFFFFu, s, o);
    __shared__ float red[4];
    if ((threadIdx.x & 31) == 0) red[threadIdx.x >> 5] = s;
    __syncthreads();
    if (threadIdx.x == 0) {
        float tot = red[0] + red[1] + red[2] + red[3];
        if (which) g_kn[row] = (row < NROWS) ? tot : 1e30f;  // pad key -> weight 0
        else       g_qn[row] = tot;
    }
}

// ---------------- kernel 3: fused RBF attention ----------------------------
// BM=64 queries/CTA, BN=64 keys/tile, d=128. 256 threads (16x16).
// smem layout (bytes):
//   Qt  [128][68]  @ 0       (34816)
//   Kt  [128][68]  @ 34816   (34816)
//   Vs  [64][128]  @ 69632   (32768)
//   Pt  [64][68]   @ 102400  (17408)   -- P transposed: [key][query]
//   qn_s[64]       @ 119808
//   kn_s[64]       @ 120064
// total 120320 B
__global__ __launch_bounds__(256) void attn_kernel(const float* __restrict__ X,
                                                   float* __restrict__ out)
{
    extern __shared__ char smem[];
    float* Qt   = (float*)smem;
    float* Kt   = (float*)(smem + 34816);
    float* Vs   = (float*)(smem + 69632);
    float* Pt   = (float*)(smem + 102400);
    float* qn_s = (float*)(smem + 119808);
    float* kn_s = (float*)(smem + 120064);

    const int tid = threadIdx.x;
    const int tr  = tid >> 4, tc = tid & 15;
    const int r0  = blockIdx.x * 64;

    // Q tile (X rows r0..r0+63; row 8191 exists in X, output guarded later)
    #pragma unroll
    for (int s = 0; s < 32; s++) {
        int e = tid + s * 256;
        int row = e >> 7, k = e & 127;
        Qt[k * 68 + row] = X[(r0 + row) * 128 + k];
    }
    if (tid < 64) qn_s[tid] = g_qn[r0 + tid];
    __syncthreads();

    float acc[4][8];
    float den[4] = {0.f, 0.f, 0.f, 0.f};
    #pragma unroll
    for (int i = 0; i < 4; i++)
        #pragma unroll
        for (int j = 0; j < 8; j++) acc[i][j] = 0.0f;

    const float4* Qt4 = (const float4*)Qt;   // stride 17
    const float4* Kt4 = (const float4*)Kt;   // stride 17
    const float4* Vs4 = (const float4*)Vs;   // stride 32
    float4*       VsW = (float4*)Vs;
    const float4* Pt4 = (const float4*)Pt;   // stride 17
    float4*       PtW = (float4*)Pt;
    const float4* X4  = (const float4*)X;

    float qnv[4];
    #pragma unroll
    for (int i = 0; i < 4; i++) qnv[i] = qn_s[tr * 4 + i];

    for (int tile = 0; tile < 128; tile++) {
        const int j0 = tile * 64;

        // ---- stage K (transposed), V, kn ----
        #pragma unroll
        for (int s = 0; s < 32; s++) {
            int e = tid + s * 256;
            int row = e >> 7, k = e & 127;
            Kt[k * 68 + row] = g_yt[(j0 + row) * 128 + k];
        }
        #pragma unroll
        for (int s = 0; s < 8; s++) {
            int idx = tid + s * 256;          // float4 index 0..2047
            int row = idx >> 5, c4 = idx & 31;
            int jg = j0 + row;
            float4 v = (jg < NROWS) ? X4[(jg + 1) * 32 + c4]
                                    : make_float4(0.f, 0.f, 0.f, 0.f);
            VsW[row * 32 + c4] = v;
        }
        if (tid < 64) kn_s[tid] = g_kn[j0 + tid];
        __syncthreads();

        // ---- S = Q @ K^T (4x4 per thread) ----
        float sa[4][4];
        #pragma unroll
        for (int i = 0; i < 4; i++)
            #pragma unroll
            for (int j = 0; j < 4; j++) sa[i][j] = 0.0f;

        #pragma unroll 8
        for (int k = 0; k < 128; k++) {
            float4 a = Qt4[k * 17 + tr];
            float4 b = Kt4[k * 17 + tc];
            float av[4] = {a.x, a.y, a.z, a.w};
            float bv[4] = {b.x, b.y, b.z, b.w};
            #pragma unroll
            for (int i = 0; i < 4; i++)
                #pragma unroll
                for (int j = 0; j < 4; j++) sa[i][j] += av[i] * bv[j];
        }

        // ---- P = exp(-gamma * clip(qn + kn - 2S, 0)) ; store transposed ----
        #pragma unroll
        for (int j = 0; j < 4; j++) {
            float knc = kn_s[tc * 4 + j];
            float4 p;
            p.x = __expf(-GAMMAK * fmaxf(fmaf(-2.0f, sa[0][j], qnv[0] + knc), 0.0f));
            p.y = __expf(-GAMMAK * fmaxf(fmaf(-2.0f, sa[1][j], qnv[1] + knc), 0.0f));
            p.z = __expf(-GAMMAK * fmaxf(fmaf(-2.0f, sa[2][j], qnv[2] + knc), 0.0f));
            p.w = __expf(-GAMMAK * fmaxf(fmaf(-2.0f, sa[3][j], qnv[3] + knc), 0.0f));
            PtW[(tc * 4 + j) * 17 + tr] = p;  // Pt[key][query], STS.128
        }
        __syncthreads();

        // ---- acc += P @ V ; den += rowsum(P) ----
        #pragma unroll 4
        for (int j = 0; j < 64; j++) {
            float4 p  = Pt4[j * 17 + tr];
            float4 v0 = Vs4[j * 32 + tc * 2];
            float4 v1 = Vs4[j * 32 + tc * 2 + 1];
            float pa[4] = {p.x, p.y, p.z, p.w};
            float vv[8] = {v0.x, v0.y, v0.z, v0.w, v1.x, v1.y, v1.z, v1.w};
            #pragma unroll
            for (int i = 0; i < 4; i++) {
                den[i] += pa[i];
                #pragma unroll
                for (int c = 0; c < 8; c++) acc[i][c] += pa[i] * vv[c];
            }
        }
        __syncthreads();   // before next tile overwrites Kt/Vs/kn_s
    }

    // ---- normalize + write ----
    float4* out4 = (float4*)out;
    #pragma unroll
    for (int i = 0; i < 4; i++) {
        int row = r0 + tr * 4 + i;
        if (row < NROWS) {
            float inv = 1.0f / den[i];
            float4 o0, o1;
            o0.x = acc[i][0] * inv;  o0.y = acc[i][1] * inv;
            o0.z = acc[i][2] * inv;  o0.w = acc[i][3] * inv;
            o1.x = acc[i][4] * inv;  o1.y = acc[i][5] * inv;
            o1.z = acc[i][6] * inv;  o1.w = acc[i][7] * inv;
            out4[row * 32 + tc * 2]     = o0;
            out4[row * 32 + tc * 2 + 1] = o1;
        }
    }
}

// ---------------- launch ----------------------------------------------------
extern "C" void kernel_launch(void* const* d_in, const int* in_sizes, int n_in,
                              void* d_out, int out_size)
{
    const float* X = (const float*)d_in[0];   // (8192,128)
    const float* y = (const float*)d_in[1];   // (8191,128)
    // d_in[2] = y_next : unused by reference output
    const float* R = (const float*)d_in[3];   // (128,128)
    const float* t = (const float*)d_in[4];   // (128,1)
    float* out = (float*)d_out;               // (8191,128)

    cudaFuncSetAttribute(yt_kernel,  cudaFuncAttributeMaxDynamicSharedMemorySize, 102400);
    cudaFuncSetAttribute(attn_kernel, cudaFuncAttributeMaxDynamicSharedMemorySize, 120320);

    yt_kernel<<<128, 256, 102400>>>(y, R, t);
    norm_kernel<<<dim3(8192, 2), 128>>>(X);
    attn_kernel<<<128, 256, 120320>>>(X, out);
}

// round 7
// speedup vs baseline: 3.8011x; 3.7974x over previous
#include <cuda_runtime.h>
#include <cstdint>

#define NROWS 8191
#define C2    0.011271055006945017f    /* 2*gamma*log2(e), gamma=1/256 */
#define NGL2  0.0056355275034725085f   /* gamma*log2(e) */

// ---------------- device scratch (no allocation allowed) ----------------
__device__ float g_yt[8192 * 128];   // tf32-rounded yt (keys)
__device__ float g_vt[8192 * 128];   // tf32-rounded V rows: g_vt[j] = X[min(j+1,8191)]
__device__ float g_cq[8192];         // -gamma*log2e*||x_i||^2 (rounded x)
__device__ float g_ck[8192];         // -gamma*log2e*||yt_j||^2 ; row 8191 -> -1e30

// ---------------- helpers ----------------
__device__ __forceinline__ float tf32r(float x) {
    uint32_t u; asm("cvt.rna.tf32.f32 %0, %1;" : "=r"(u) : "f"(x));
    return __uint_as_float(u);
}
__device__ __forceinline__ float ex2f(float x) {
    float r; asm("ex2.approx.f32 %0, %1;" : "=f"(r) : "f"(x)); return r;
}
__device__ __forceinline__ uint32_t smaddr(const void* p) {
    uint32_t a;
    asm("{ .reg .u64 t; cvta.to.shared.u64 t, %1; cvt.u32.u64 %0, t; }" : "=r"(a) : "l"(p));
    return a;
}
#define CP16(dst, src) \
    asm volatile("cp.async.cg.shared.global [%0], [%1], 16;" \
                 :: "r"(dst), "l"((size_t)__cvta_generic_to_global(src)) : "memory")
#define CP_COMMIT() asm volatile("cp.async.commit_group;" ::: "memory")
#define CP_WAIT1()  asm volatile("cp.async.wait_group 1;" ::: "memory")
#define CP_WAIT0()  asm volatile("cp.async.wait_group 0;" ::: "memory")

__device__ __forceinline__ void mma8(float* c, uint32_t a0, uint32_t a1, uint32_t a2,
                                     uint32_t a3, uint32_t b0, uint32_t b1) {
    asm volatile("mma.sync.aligned.m16n8k8.row.col.f32.tf32.tf32.f32 "
                 "{%0,%1,%2,%3}, {%4,%5,%6,%7}, {%8,%9}, {%0,%1,%2,%3};"
                 : "+f"(c[0]), "+f"(c[1]), "+f"(c[2]), "+f"(c[3])
                 : "r"(a0), "r"(a1), "r"(a2), "r"(a3), "r"(b0), "r"(b1));
}

// ---------------- kernel 1: yt = y @ R^T + t (tf32-rounded at store) --------
__global__ __launch_bounds__(256) void yt_kernel(const float* __restrict__ y,
                                                 const float* __restrict__ R,
                                                 const float* __restrict__ t)
{
    extern __shared__ char smem[];
    float* yT = (float*)smem;                 // [k][row] stride 68
    float* RT = (float*)(smem + 34816);       // [k][c]   stride 132
    const int tid = threadIdx.x;
    const int r0  = blockIdx.x * 64;

    #pragma unroll
    for (int s = 0; s < 32; s++) {
        int e = tid + s * 256, row = e >> 7, k = e & 127, gr = r0 + row;
        yT[k * 68 + row] = (gr < NROWS) ? y[gr * 128 + k] : 0.0f;
    }
    #pragma unroll
    for (int s = 0; s < 64; s++) {
        int e = tid + s * 256, c = e >> 7, k = e & 127;
        RT[k * 132 + c] = R[e];
    }
    __syncthreads();

    const int tr = tid >> 4, tc = tid & 15;
    float acc[4][8];
    #pragma unroll
    for (int i = 0; i < 4; i++)
        #pragma unroll
        for (int j = 0; j < 8; j++) acc[i][j] = 0.0f;

    const float4* yT4 = (const float4*)yT;
    const float4* RT4 = (const float4*)RT;
    #pragma unroll 8
    for (int k = 0; k < 128; k++) {
        float4 a  = yT4[k * 17 + tr];
        float4 b0 = RT4[k * 33 + tc * 2];
        float4 b1 = RT4[k * 33 + tc * 2 + 1];
        float av[4] = {a.x, a.y, a.z, a.w};
        float bv[8] = {b0.x, b0.y, b0.z, b0.w, b1.x, b1.y, b1.z, b1.w};
        #pragma unroll
        for (int i = 0; i < 4; i++)
            #pragma unroll
            for (int j = 0; j < 8; j++) acc[i][j] += av[i] * bv[j];
    }
    float tv[8];
    #pragma unroll
    for (int j = 0; j < 8; j++) tv[j] = t[tc * 8 + j];
    float4* yt4 = (float4*)g_yt;
    #pragma unroll
    for (int i = 0; i < 4; i++) {
        int row = r0 + tr * 4 + i;
        float4 o0, o1;
        o0.x = tf32r(acc[i][0] + tv[0]); o0.y = tf32r(acc[i][1] + tv[1]);
        o0.z = tf32r(acc[i][2] + tv[2]); o0.w = tf32r(acc[i][3] + tv[3]);
        o1.x = tf32r(acc[i][4] + tv[4]); o1.y = tf32r(acc[i][5] + tv[5]);
        o1.z = tf32r(acc[i][6] + tv[6]); o1.w = tf32r(acc[i][7] + tv[7]);
        yt4[row * 32 + tc * 2]     = o0;
        yt4[row * 32 + tc * 2 + 1] = o1;
    }
}

// ---------------- kernel 2: scaled norms (from the values MMA will see) ----
__global__ __launch_bounds__(128) void norm_kernel(const float* __restrict__ X)
{
    const int row = blockIdx.x, which = blockIdx.y;
    float v = which ? g_yt[row * 128 + threadIdx.x]
                    : tf32r(X[row * 128 + threadIdx.x]);
    float s = v * v;
    #pragma unroll
    for (int o = 16; o; o >>= 1) s += __shfl_down_sync(0xFFFFFFFFu, s, o);
    __shared__ float red[4];
    if ((threadIdx.x & 31) == 0) red[threadIdx.x >> 5] = s;
    __syncthreads();
    if (threadIdx.x == 0) {
        float tot = -(red[0] + red[1] + red[2] + red[3]) * NGL2;
        if (which) g_ck[row] = (row < NROWS) ? tot : -1e30f;
        else       g_cq[row] = tot;
    }
}

// ---------------- kernel 3: V rows (shifted, clamped, tf32-rounded) --------
__global__ __launch_bounds__(256) void vt_kernel(const float* __restrict__ X)
{
    int f = blockIdx.x * 256 + threadIdx.x;     // float4 index, 262144 total
    int row = f >> 5, c4 = f & 31;
    int src = row + 1; if (src > 8191) src = 8191;   // clamp; weight is 0 anyway
    float4 v = ((const float4*)X)[src * 32 + c4];
    v.x = tf32r(v.x); v.y = tf32r(v.y); v.z = tf32r(v.z); v.w = tf32r(v.w);
    ((float4*)g_vt)[f] = v;
}

// ---------------- kernel 4: flash RBF attention, tf32 mma.sync --------------
// grid 128, 128 threads (4 warps, warp w owns rows m0=w*16 .. m0+15).
// smem (floats): Qs[64][132]@0  Ks[2][64][132]@8448  Vs[2][64][136]@25344
//                Ps[64][76]@42752  ck[2][64]@47616   total 47744 f = 190976 B
#define SQ 132
#define SV 136
#define SP 76
#define QSO 0
#define KSO(b) (8448 + (b) * 8448)
#define VSO(b) (25344 + (b) * 8704)
#define PSO 42752
#define CKO(b) (47616 + (b) * 64)
#define SMEM_BYTES (47744 * 4)

__global__ __launch_bounds__(128, 1) void attn_kernel(const float* __restrict__ X,
                                                      float* __restrict__ out)
{
    extern __shared__ float sm[];
    const int tid = threadIdx.x;
    const int w = tid >> 5, l = tid & 31;
    const int gid = l >> 2, tig = l & 3;
    const int m0 = w * 16;
    const int r0 = blockIdx.x * 64;

    // ---- stage Q (tf32-rounded) into Qs ----
    {
        const float4* X4 = (const float4*)X;
        #pragma unroll
        for (int i = 0; i < 16; i++) {
            int f = tid + i * 128, r = f >> 5, c4 = f & 31;
            float4 q = X4[(size_t)(r0 + r) * 32 + c4];
            float* d = &sm[QSO + r * SQ + c4 * 4];
            d[0] = tf32r(q.x); d[1] = tf32r(q.y); d[2] = tf32r(q.z); d[3] = tf32r(q.w);
        }
    }
    const float cq0 = g_cq[r0 + m0 + gid];
    const float cq1 = g_cq[r0 + m0 + gid + 8];

    // ---- prime tile 0 into buffer 0 ----
    #pragma unroll
    for (int i = 0; i < 16; i++) {
        int f = tid + i * 128, r = f >> 5, c4 = f & 31;
        CP16(smaddr(&sm[KSO(0) + r * SQ + c4 * 4]), g_yt + r * 128 + c4 * 4);
    }
    #pragma unroll
    for (int i = 0; i < 16; i++) {
        int f = tid + i * 128, r = f >> 5, c4 = f & 31;
        CP16(smaddr(&sm[VSO(0) + r * SV + c4 * 4]), g_vt + r * 128 + c4 * 4);
    }
    if (tid < 16) CP16(smaddr(&sm[CKO(0) + tid * 4]), g_ck + tid * 4);
    CP_COMMIT();

    float oa[16][4];
    #pragma unroll
    for (int i = 0; i < 16; i++)
        #pragma unroll
        for (int j = 0; j < 4; j++) oa[i][j] = 0.0f;
    float den0 = 0.0f, den1 = 0.0f;

    #pragma unroll 1
    for (int t = 0; t < 128; t++) {
        const int b = t & 1;

        if (t + 1 < 128) {                      // prefetch t+1 into buf b^1
            const int nb = b ^ 1;
            const int j0 = (t + 1) * 64;
            #pragma unroll
            for (int i = 0; i < 16; i++) {
                int f = tid + i * 128, r = f >> 5, c4 = f & 31;
                CP16(smaddr(&sm[KSO(nb) + r * SQ + c4 * 4]),
                     g_yt + (size_t)(j0 + r) * 128 + c4 * 4);
            }
            #pragma unroll
            for (int i = 0; i < 16; i++) {
                int f = tid + i * 128, r = f >> 5, c4 = f & 31;
                CP16(smaddr(&sm[VSO(nb) + r * SV + c4 * 4]),
                     g_vt + (size_t)(j0 + r) * 128 + c4 * 4);
            }
            if (tid < 16) CP16(smaddr(&sm[CKO(nb) + tid * 4]), g_ck + j0 + tid * 4);
            CP_COMMIT();
            CP_WAIT1();                          // tile t fully arrived
        } else {
            CP_WAIT0();
        }
        __syncthreads();

        // ---- GEMM1: S = Q @ K^T  (m16 x n64 x k128 per warp) ----
        float sa[8][4];
        #pragma unroll
        for (int i = 0; i < 8; i++)
            #pragma unroll
            for (int j = 0; j < 4; j++) sa[i][j] = 0.0f;

        const uint32_t* QsU = (const uint32_t*)&sm[QSO];
        const uint32_t* KsU = (const uint32_t*)&sm[KSO(b)];
        #pragma unroll
        for (int k0 = 0; k0 < 16; k0++) {
            uint32_t a0 = QsU[(m0 + gid) * SQ + k0 * 8 + tig];
            uint32_t a1 = QsU[(m0 + gid + 8) * SQ + k0 * 8 + tig];
            uint32_t a2 = QsU[(m0 + gid) * SQ + k0 * 8 + tig + 4];
            uint32_t a3 = QsU[(m0 + gid + 8) * SQ + k0 * 8 + tig + 4];
            #pragma unroll
            for (int n0 = 0; n0 < 8; n0++) {
                uint32_t b0 = KsU[(n0 * 8 + gid) * SQ + k0 * 8 + tig];
                uint32_t b1 = KsU[(n0 * 8 + gid) * SQ + k0 * 8 + tig + 4];
                mma8(sa[n0], a0, a1, a2, a3, b0, b1);
            }
        }

        // ---- P = 2^(C2*S + cq + ck) (tf32-rounded), den += P, store Ps ----
        const float* ckb = &sm[CKO(b)];
        float* Ps = &sm[PSO + m0 * SP];
        #pragma unroll
        for (int n0 = 0; n0 < 8; n0++) {
            float ck0 = ckb[n0 * 8 + 2 * tig], ck1 = ckb[n0 * 8 + 2 * tig + 1];
            float p00 = tf32r(ex2f(fmaf(C2, sa[n0][0], cq0 + ck0)));
            float p01 = tf32r(ex2f(fmaf(C2, sa[n0][1], cq0 + ck1)));
            float p10 = tf32r(ex2f(fmaf(C2, sa[n0][2], cq1 + ck0)));
            float p11 = tf32r(ex2f(fmaf(C2, sa[n0][3], cq1 + ck1)));
            den0 += p00 + p01;
            den1 += p10 + p11;
            *(float2*)&Ps[gid * SP + n0 * 8 + 2 * tig]       = make_float2(p00, p01);
            *(float2*)&Ps[(gid + 8) * SP + n0 * 8 + 2 * tig] = make_float2(p10, p11);
        }
        __syncwarp();

        // ---- GEMM2: O += P @ V  (m16 x n128 x k64 per warp) ----
        const uint32_t* PsU = (const uint32_t*)Ps;
        const uint32_t* VsU = (const uint32_t*)&sm[VSO(b)];
        #pragma unroll
        for (int k0 = 0; k0 < 8; k0++) {
            uint32_t a0 = PsU[gid * SP + k0 * 8 + tig];
            uint32_t a1 = PsU[(gid + 8) * SP + k0 * 8 + tig];
            uint32_t a2 = PsU[gid * SP + k0 * 8 + tig + 4];
            uint32_t a3 = PsU[(gid + 8) * SP + k0 * 8 + tig + 4];
            #pragma unroll
            for (int n0 = 0; n0 < 16; n0++) {
                uint32_t b0 = VsU[(k0 * 8 + tig) * SV + n0 * 8 + gid];
                uint32_t b1 = VsU[(k0 * 8 + tig + 4) * SV + n0 * 8 + gid];
                mma8(oa[n0], a0, a1, a2, a3, b0, b1);
            }
        }
        __syncthreads();                         // release buf b for tile t+2
    }

    // ---- reduce den across the 4 lanes sharing a row, normalize, write ----
    den0 += __shfl_xor_sync(0xFFFFFFFFu, den0, 1);
    den0 += __shfl_xor_sync(0xFFFFFFFFu, den0, 2);
    den1 += __shfl_xor_sync(0xFFFFFFFFu, den1, 1);
    den1 += __shfl_xor_sync(0xFFFFFFFFu, den1, 2);
    const float i0 = 1.0f / den0, i1 = 1.0f / den1;
    const int row0 = r0 + m0 + gid, row1 = row0 + 8;
    #pragma unroll
    for (int n0 = 0; n0 < 16; n0++) {
        int col = n0 * 8 + 2 * tig;
        if (row0 < NROWS)
            *(float2*)&out[(size_t)row0 * 128 + col] =
                make_float2(oa[n0][0] * i0, oa[n0][1] * i0);
        if (row1 < NROWS)
            *(float2*)&out[(size_t)row1 * 128 + col] =
                make_float2(oa[n0][2] * i1, oa[n0][3] * i1);
    }
}

// ---------------- launch ----------------------------------------------------
extern "C" void kernel_launch(void* const* d_in, const int* in_sizes, int n_in,
                              void* d_out, int out_size)
{
    const float* X = (const float*)d_in[0];   // (8192,128)
    const float* y = (const float*)d_in[1];   // (8191,128)
    const float* R = (const float*)d_in[3];   // (128,128)
    const float* t = (const float*)d_in[4];   // (128,1)
    float* out = (float*)d_out;               // (8191,128)

    cudaFuncSetAttribute(yt_kernel,   cudaFuncAttributeMaxDynamicSharedMemorySize, 102400);
    cudaFuncSetAttribute(attn_kernel, cudaFuncAttributeMaxDynamicSharedMemorySize, SMEM_BYTES);

    yt_kernel<<<128, 256, 102400>>>(y, R, t);
    norm_kernel<<<dim3(8192, 2), 128>>>(X);
    vt_kernel<<<1024, 256>>>(X);
    attn_kernel<<<128, 128, SMEM_BYTES>>>(X, out);
}